// round 15
// baseline (speedup 1.0000x reference)
#include <cuda_runtime.h>
#include <cuda_bf16.h>
#include <cstdint>
#include <math.h>

namespace {

// ===========================================================================
// Warp-MMA helpers (baseline PTX, works on plain sm_103 target)
// ===========================================================================
__device__ __forceinline__ uint32_t smem_to_u32(const void* smem_ptr) {
    uint32_t addr;
    asm("{ .reg .u64 tmp; cvta.to.shared.u64 tmp, %1; cvt.u32.u64 %0, tmp; }"
        : "=r"(addr) : "l"(smem_ptr));
    return addr;
}

#define SMEM_SWIZZLE_128B(byte_offset) \
    ((byte_offset) ^ (((byte_offset) >> 3) & 0x70))

__device__ __forceinline__ void ldsm4(uint32_t* r, uint32_t addr) {
    asm volatile("ldmatrix.sync.aligned.m8n8.x4.shared.b16 {%0,%1,%2,%3}, [%4];"
                 : "=r"(r[0]), "=r"(r[1]), "=r"(r[2]), "=r"(r[3]) : "r"(addr));
}

__device__ __forceinline__ void mma16816(float* c, const uint32_t* a, const uint32_t* b) {
    asm volatile(
        "mma.sync.aligned.m16n8k16.row.col.f32.bf16.bf16.f32 "
        "{%0,%1,%2,%3}, {%4,%5,%6,%7}, {%8,%9}, {%0,%1,%2,%3};"
        : "+f"(c[0]), "+f"(c[1]), "+f"(c[2]), "+f"(c[3])
        : "r"(a[0]), "r"(a[1]), "r"(a[2]), "r"(a[3]), "r"(b[0]), "r"(b[1]));
}

__device__ __forceinline__ void cp16(uint32_t dst_smem, const void* src) {
    asm volatile("cp.async.cg.shared.global [%0], [%1], 16;"
                 :: "r"(dst_smem), "l"(__cvta_generic_to_global(src)) : "memory");
}

// ===========================================================================
// Problem constants + scratch
// ===========================================================================
constexpr int HG  = 128;
constexpr int WG  = 128;
constexpr int NQ  = HG * WG;        // 16384
constexpr int D   = 256;
constexpr int NHD = 8;
constexpr int CINC = 384;

// converted-weight buffer offsets (elements)
constexpr int W_CONVQ = 0;                       // 256x384
constexpr int W_CONVV = 98304;                   // 256x384
constexpr int W_LINQ  = 196608;                  // 256x256
constexpr int W_LINV  = 262144;                  // 256x256
constexpr int W_VP    = 327680;                  // 4 x 256x256 (layers contiguous)
constexpr int W_OFFAW = 589824;                  // 4 x 96x256 (off 64 rows + aw 32 rows)
constexpr int W_OP    = 688128;                  // 4 x 256x256
constexpr int W_O1    = 950272;                  // 128x256
constexpr int W_O2    = 983040;                  // 64x128
constexpr int W_O3    = 991232;                  // 384x64
constexpr int W_TOTAL = 1015808;

// fp32 scratch
__device__ float g_pos  [NQ * D];
__device__ float g_q    [NQ * D];
__device__ float g_val3 [NQ * 768];   // merged vp output, layers 0-2
__device__ float g_val  [NQ * D];     // layer-3 vp output
__device__ float g_offaw[NQ * 96];    // merged off(64)+aw(32)
__device__ float g_h1f  [NQ * 128];
__device__ float g_h2f  [NQ * 64];
__device__ float g_packb[4 * 96];     // packed off/aw biases

// bf16 hi/lo scratch
__device__ __nv_bfloat16 g_cq_h[NQ * CINC], g_cq_l[NQ * CINC];
__device__ __nv_bfloat16 g_cv_h[NQ * CINC], g_cv_l[NQ * CINC];
__device__ __nv_bfloat16 g_t_h [NQ * D],    g_t_l [NQ * D];
__device__ __nv_bfloat16 g_vb_h[NQ * D],    g_vb_l[NQ * D];
__device__ __nv_bfloat16 g_qb_h[NQ * D],    g_qb_l[NQ * D];
__device__ __nv_bfloat16 g_qp_h[NQ * D],    g_qp_l[NQ * D];
__device__ __nv_bfloat16 g_sp_h[NQ * D],    g_sp_l[NQ * D];
__device__ __nv_bfloat16 g_h1_h[NQ * 128],  g_h1_l[NQ * 128];
__device__ __nv_bfloat16 g_h2_h[NQ * 64],   g_h2_l[NQ * 64];
__device__ __nv_bfloat16 g_w_h [W_TOTAL],   g_w_l [W_TOTAL];

__device__ __forceinline__ void f2bf2(float v, __nv_bfloat16& h, __nv_bfloat16& l)
{
    h = __float2bfloat16(v);
    l = __float2bfloat16(v - __bfloat162float(h));
}

// ===========================================================================
// Tensor-core split-bf16 GEMM via mma.sync + cp.async double buffering.
//   POSADD: epilogue additionally writes Phi/Plo = split(v + pos[m*N + col]).
// ===========================================================================
template<int BN, bool WF32, bool WBF16, bool RES, bool STORE_T, bool POSADD>
__global__ void __launch_bounds__(256)
gemm_mma(const __nv_bfloat16* __restrict__ Ahi, const __nv_bfloat16* __restrict__ Alo,
         const __nv_bfloat16* __restrict__ Bhi, const __nv_bfloat16* __restrict__ Blo,
         const float* __restrict__ bias, const float* __restrict__ res,
         float* __restrict__ C, __nv_bfloat16* __restrict__ Chi,
         __nv_bfloat16* __restrict__ Clo,
         const float* __restrict__ pos, __nv_bfloat16* __restrict__ Phi,
         __nv_bfloat16* __restrict__ Plo, int M, int N, int K)
{
    constexpr int WNT = BN / 2;
    constexpr int NF  = WNT / 8;
    constexpr int OFF_ALO = 16384;
    constexpr int OFF_BHI = 32768;
    constexpr int OFF_BLO = 32768 + BN * 128;
    constexpr int STAGE   = 32768 + 2 * BN * 128;

    extern __shared__ char dynsmem[];
    const uint32_t smem_u32 = smem_to_u32(dynsmem);

    const int tid  = threadIdx.x;
    const int lane = tid & 31;
    const int wid  = tid >> 5;
    const int wm   = wid & 3;
    const int wn   = wid >> 2;
    const int m0   = blockIdx.y * 128;
    const int n0   = blockIdx.x * BN;

    float acc[2][NF][4];
#pragma unroll
    for (int i = 0; i < 2; i++)
#pragma unroll
        for (int j = 0; j < NF; j++)
#pragma unroll
            for (int k = 0; k < 4; k++) acc[i][j][k] = 0.f;

    const int a_row = (lane & 7) + ((lane >> 3) & 1) * 8;
    const int a_koff = (lane >> 4) * 8;
    const int b_row = (lane >> 4) * 8 + (lane & 7);
    const int b_koff = ((lane >> 3) & 1) * 8;

    auto load_chunk = [&](int stage, int k0) {
        const uint32_t base = smem_u32 + stage * STAGE;
#pragma unroll
        for (int u = tid; u < 2048; u += 256) {
            const int half = u >> 10;
            const int uu   = u & 1023;
            const int row  = uu >> 3;
            const int c16  = uu & 7;
            const __nv_bfloat16* src =
                (half ? Alo : Ahi) + (size_t)(m0 + row) * K + k0 + c16 * 8;
            cp16(base + (half ? OFF_ALO : 0) +
                 SMEM_SWIZZLE_128B(row * 128 + c16 * 16), src);
        }
#pragma unroll
        for (int u = tid; u < 2 * BN * 8; u += 256) {
            const int half = (u >= BN * 8);
            const int uu   = half ? u - BN * 8 : u;
            const int row  = uu >> 3;
            const int c16  = uu & 7;
            const __nv_bfloat16* src =
                (half ? Blo : Bhi) + (size_t)(n0 + row) * K + k0 + c16 * 8;
            cp16(base + (half ? OFF_BLO : OFF_BHI) +
                 SMEM_SWIZZLE_128B(row * 128 + c16 * 16), src);
        }
        asm volatile("cp.async.commit_group;" ::: "memory");
    };

    const int nchunks = K >> 6;
    load_chunk(0, 0);

    for (int c = 0; c < nchunks; c++) {
        if (c + 1 < nchunks) {
            load_chunk((c + 1) & 1, (c + 1) << 6);
            asm volatile("cp.async.wait_group 1;" ::: "memory");
        } else {
            asm volatile("cp.async.wait_group 0;" ::: "memory");
        }
        __syncthreads();

        const uint32_t base = smem_u32 + (c & 1) * STAGE;
        const uint32_t sA0 = base;
        const uint32_t sA1 = base + OFF_ALO;
        const uint32_t sB0 = base + OFF_BHI;
        const uint32_t sB1 = base + OFF_BLO;

#pragma unroll
        for (int ks = 0; ks < 4; ks++) {
            const int kw = ks * 16;
            uint32_t ah[2][4], al[2][4];
#pragma unroll
            for (int mb = 0; mb < 2; mb++) {
                const int row = wm * 32 + mb * 16 + a_row;
                const uint32_t off = SMEM_SWIZZLE_128B(row * 128 + (kw + a_koff) * 2);
                ldsm4(ah[mb], sA0 + off);
                ldsm4(al[mb], sA1 + off);
            }
            uint32_t bh[NF][2], bl[NF][2];
#pragma unroll
            for (int pr = 0; pr < NF / 2; pr++) {
                const int row = wn * WNT + pr * 16 + b_row;
                const uint32_t off = SMEM_SWIZZLE_128B(row * 128 + (kw + b_koff) * 2);
                uint32_t t[4];
                ldsm4(t, sB0 + off);
                bh[pr * 2][0] = t[0]; bh[pr * 2][1] = t[1];
                bh[pr * 2 + 1][0] = t[2]; bh[pr * 2 + 1][1] = t[3];
                ldsm4(t, sB1 + off);
                bl[pr * 2][0] = t[0]; bl[pr * 2][1] = t[1];
                bl[pr * 2 + 1][0] = t[2]; bl[pr * 2 + 1][1] = t[3];
            }
#pragma unroll
            for (int mb = 0; mb < 2; mb++)
#pragma unroll
                for (int nf = 0; nf < NF; nf++) {
                    mma16816(acc[mb][nf], ah[mb], bh[nf]);
                    mma16816(acc[mb][nf], ah[mb], bl[nf]);
                    mma16816(acc[mb][nf], al[mb], bh[nf]);
                }
        }
        __syncthreads();
    }

    // ---- epilogue ---------------------------------------------------------
#pragma unroll
    for (int mb = 0; mb < 2; mb++) {
#pragma unroll
        for (int part = 0; part < 2; part++) {
            const int m = m0 + wm * 32 + mb * 16 + part * 8 + (lane >> 2);
#pragma unroll
            for (int nf = 0; nf < NF; nf++) {
                const int col = n0 + wn * WNT + nf * 8 + (lane & 3) * 2;
                float v0 = acc[mb][nf][part * 2 + 0] + bias[col];
                float v1 = acc[mb][nf][part * 2 + 1] + bias[col + 1];
                if (RES) {
                    const float2 r2 = *(const float2*)(res + (size_t)m * N + col);
                    v0 += r2.x; v1 += r2.y;
                }
                if (STORE_T) {
                    C[(size_t)col * M + m] = v0;
                    C[(size_t)(col + 1) * M + m] = v1;
                } else if (WF32) {
                    *(float2*)(C + (size_t)m * N + col) = make_float2(v0, v1);
                }
                if (WBF16) {
                    __nv_bfloat16 h0, l0, h1, l1;
                    f2bf2(v0, h0, l0);
                    f2bf2(v1, h1, l1);
                    Chi[(size_t)m * N + col] = h0; Chi[(size_t)m * N + col + 1] = h1;
                    Clo[(size_t)m * N + col] = l0; Clo[(size_t)m * N + col + 1] = l1;
                }
                if (POSADD) {
                    const float2 p2 = *(const float2*)(pos + (size_t)m * N + col);
                    __nv_bfloat16 h0, l0, h1, l1;
                    f2bf2(v0 + p2.x, h0, l0);
                    f2bf2(v1 + p2.y, h1, l1);
                    Phi[(size_t)m * N + col] = h0; Phi[(size_t)m * N + col + 1] = h1;
                    Plo[(size_t)m * N + col] = l0; Plo[(size_t)m * N + col + 1] = l1;
                }
            }
        }
    }
}

// ===========================================================================
// Elementwise / conversion kernels
// ===========================================================================
__global__ void pos_kernel(const float* __restrict__ row_embed,
                           const float* __restrict__ col_embed,
                           float* __restrict__ pos)
{
    const int idx = blockIdx.x * blockDim.x + threadIdx.x;
    if (idx >= NQ * D) return;
    const int p = idx >> 8;
    const int d = idx & 255;
    const int h = p >> 7;
    const int w = p & 127;
    pos[idx] = (d < 128) ? col_embed[w * 128 + d] : row_embed[h * 128 + (d - 128)];
}

// pack off/aw biases into [4][96]
__global__ void packb_kernel(const float* __restrict__ off_b,
                             const float* __restrict__ aw_b,
                             float* __restrict__ out)
{
    const int i = threadIdx.x;       // 0..383
    if (i >= 384) return;
    const int layer = i / 96;
    const int j = i % 96;
    out[i] = (j < 64) ? off_b[layer * 64 + j] : aw_b[layer * 32 + (j - 64)];
}

// channel-major fp32 [K,M] -> hi/lo bf16 [M,K]
__global__ void tconvert_kernel(const float* __restrict__ src,
                                __nv_bfloat16* __restrict__ hi,
                                __nv_bfloat16* __restrict__ lo, int M, int K)
{
    __shared__ float t[32][33];
    const int tx = threadIdx.x, ty = threadIdx.y;
    const int m0 = blockIdx.x * 32, k0 = blockIdx.y * 32;
#pragma unroll
    for (int j = 0; j < 4; j++)
        t[ty + j * 8][tx] = src[(size_t)(k0 + ty + j * 8) * M + m0 + tx];
    __syncthreads();
#pragma unroll
    for (int j = 0; j < 4; j++) {
        const int m = m0 + ty + j * 8;
        const int k = k0 + tx;
        __nv_bfloat16 h, l;
        f2bf2(t[tx][ty + j * 8], h, l);
        hi[(size_t)m * K + k] = h;
        lo[(size_t)m * K + k] = l;
    }
}

// one-shot conversion of all weight matrices into [N,K] hi/lo bf16
struct WSeg { int srcSel; int srcOff; int N; int K; int kn; int dstOff; };
__device__ const WSeg d_wsegs[27] = {
    {0, 0,      256, 384, 0, W_CONVQ},
    {1, 0,      256, 384, 0, W_CONVV},
    {2, 0,      256, 256, 1, W_LINQ},
    {3, 0,      256, 256, 1, W_LINV},
    {4, 0,      256, 256, 1, W_VP + 0 * 65536},
    {4, 65536,  256, 256, 1, W_VP + 1 * 65536},
    {4, 131072, 256, 256, 1, W_VP + 2 * 65536},
    {4, 196608, 256, 256, 1, W_VP + 3 * 65536},
    {5, 0,      64, 256, 1, W_OFFAW + 0 * 24576},
    {6, 0,      32, 256, 1, W_OFFAW + 0 * 24576 + 16384},
    {5, 16384,  64, 256, 1, W_OFFAW + 1 * 24576},
    {6, 8192,   32, 256, 1, W_OFFAW + 1 * 24576 + 16384},
    {5, 32768,  64, 256, 1, W_OFFAW + 2 * 24576},
    {6, 16384,  32, 256, 1, W_OFFAW + 2 * 24576 + 16384},
    {5, 49152,  64, 256, 1, W_OFFAW + 3 * 24576},
    {6, 24576,  32, 256, 1, W_OFFAW + 3 * 24576 + 16384},
    {7, 0,      256, 256, 1, W_OP + 0 * 65536},
    {7, 65536,  256, 256, 1, W_OP + 1 * 65536},
    {7, 131072, 256, 256, 1, W_OP + 2 * 65536},
    {7, 196608, 256, 256, 1, W_OP + 3 * 65536},
    {8, 0,      128, 256, 1, W_O1},
    {9, 0,      64, 128, 1, W_O2},
    {10, 0,     384, 64, 1, W_O3},
    {10, 0,     384, 64, 1, W_O3},   // padding (dup, same data)
    {10, 0,     384, 64, 1, W_O3},
    {10, 0,     384, 64, 1, W_O3},
    {10, 0,     384, 64, 1, W_O3},
};
struct WPtrs { const float* p[11]; };

__global__ void convert_weights_kernel(WPtrs ptrs,
                                       __nv_bfloat16* __restrict__ hi,
                                       __nv_bfloat16* __restrict__ lo)
{
    const int id = blockIdx.x * blockDim.x + threadIdx.x;
    if (id >= W_TOTAL) return;
    int s = 0;
#pragma unroll
    for (int i = 1; i < 23; i++)
        if (id >= d_wsegs[i].dstOff) s = i;
    const WSeg seg = d_wsegs[s];
    const int local = id - seg.dstOff;
    const int n = local / seg.K;
    const int k = local - n * seg.K;
    const float* src = ptrs.p[seg.srcSel] + seg.srcOff;
    const float v = seg.kn ? src[(size_t)k * seg.N + n] : src[(size_t)n * seg.K + k];
    __nv_bfloat16 h, l;
    f2bf2(v, h, l);
    hi[id] = h;
    lo[id] = l;
}

// softmax over the aw block (cols 64..95) of the merged offaw buffer
__global__ void softmax4_kernel(float* __restrict__ offaw)
{
    const int t = blockIdx.x * blockDim.x + threadIdx.x;
    if (t >= NQ * NHD) return;
    float* p = offaw + (size_t)(t >> 3) * 96 + 64 + (t & 7) * 4;
    float4 v = *(float4*)p;
    const float mx = fmaxf(fmaxf(v.x, v.y), fmaxf(v.z, v.w));
    const float ex = __expf(v.x - mx), ey = __expf(v.y - mx);
    const float ez = __expf(v.z - mx), ew = __expf(v.w - mx);
    const float r = 1.f / (ex + ey + ez + ew);
    *(float4*)p = make_float4(ex * r, ey * r, ez * r, ew * r);
}

// one warp per (query, head); lane = channel; reads merged offaw buffer
__global__ void msda_sample_kernel(const float* __restrict__ val, int vstride,
                                   const float* __restrict__ offaw,
                                   __nv_bfloat16* __restrict__ ohi,
                                   __nv_bfloat16* __restrict__ olo)
{
    const int warp = (blockIdx.x * blockDim.x + threadIdx.x) >> 5;
    const int lane = threadIdx.x & 31;
    if (warp >= NQ * NHD) return;
    const int p = warp >> 3;
    const int hh = warp & 7;
    const int py = p >> 7;
    const int px = p & 127;

    const float* offp  = offaw + (size_t)p * 96 + hh * 8;
    const float* awp   = offaw + (size_t)p * 96 + 64 + hh * 4;
    const float* vbase = val + hh * 32 + lane;

    float acc = 0.f;
#pragma unroll
    for (int k = 0; k < 4; k++) {
        const float a  = awp[k];
        const float x  = (float)px + offp[2 * k + 0];
        const float y  = (float)py + offp[2 * k + 1];
        const float xf = floorf(x), yf = floorf(y);
        const float lx = x - xf,   ly = y - yf;
        const int   x0 = (int)xf,  y0 = (int)yf;

        const float w00 = (1.f - lx) * (1.f - ly) * a;
        const float w01 = lx * (1.f - ly) * a;
        const float w10 = (1.f - lx) * ly * a;
        const float w11 = lx * ly * a;

        const bool xv0 = (x0 >= 0)     && (x0 < WG);
        const bool xv1 = (x0 + 1 >= 0) && (x0 + 1 < WG);
        const bool yv0 = (y0 >= 0)     && (y0 < HG);
        const bool yv1 = (y0 + 1 >= 0) && (y0 + 1 < HG);

        if (yv0 && xv0) acc += w00 * vbase[(size_t)(y0 * WG + x0) * vstride];
        if (yv0 && xv1) acc += w01 * vbase[(size_t)(y0 * WG + x0 + 1) * vstride];
        if (yv1 && xv0) acc += w10 * vbase[(size_t)((y0 + 1) * WG + x0) * vstride];
        if (yv1 && xv1) acc += w11 * vbase[(size_t)((y0 + 1) * WG + x0 + 1) * vstride];
    }
    __nv_bfloat16 h, l;
    f2bf2(acc, h, l);
    ohi[(size_t)p * D + hh * 32 + lane] = h;
    olo[(size_t)p * D + hh * 32 + lane] = l;
}

// LayerNorm + ReLU, writes bf16 hi/lo
template<int WID>
__global__ void ln_relu_kernel(const float* __restrict__ x,
                               const float* __restrict__ g,
                               const float* __restrict__ b,
                               __nv_bfloat16* __restrict__ ohi,
                               __nv_bfloat16* __restrict__ olo)
{
    const int row  = (blockIdx.x * blockDim.x + threadIdx.x) >> 5;
    const int lane = threadIdx.x & 31;
    if (row >= NQ) return;
    const float* xr = x + (size_t)row * WID;
    constexpr int PER = WID / 32;
    float v[PER];
    float s = 0.f, s2 = 0.f;
#pragma unroll
    for (int i = 0; i < PER; i++) {
        v[i] = xr[lane + 32 * i];
        s  += v[i];
        s2 += v[i] * v[i];
    }
#pragma unroll
    for (int o = 16; o > 0; o >>= 1) {
        s  += __shfl_xor_sync(0xffffffffu, s,  o);
        s2 += __shfl_xor_sync(0xffffffffu, s2, o);
    }
    const float mean = s / WID;
    const float var  = s2 / WID - mean * mean;
    const float inv  = rsqrtf(var + 1e-5f);
#pragma unroll
    for (int i = 0; i < PER; i++) {
        const int c = lane + 32 * i;
        const float o = fmaxf((v[i] - mean) * inv * g[c] + b[c], 0.f);
        __nv_bfloat16 h, l;
        f2bf2(o, h, l);
        ohi[(size_t)row * WID + c] = h;
        olo[(size_t)row * WID + c] = l;
    }
}

void* devptr(const void* symbol)
{
    void* p = nullptr;
    cudaGetSymbolAddress(&p, symbol);
    return p;
}

constexpr int SMEM64 = 2 * (32768 + 2 * 64 * 128);   // 98304
constexpr int SMEM32 = 2 * (32768 + 2 * 32 * 128);   // 81920

} // anonymous namespace

// ===========================================================================
// Launch sequence
// ===========================================================================
extern "C" void kernel_launch(void* const* d_in, const int* in_sizes, int n_in,
                              void* d_out, int out_size)
{
    const float* query      = (const float*)d_in[0];
    const float* value      = (const float*)d_in[1];
    const float* conv_q_w   = (const float*)d_in[2];
    const float* conv_q_b   = (const float*)d_in[3];
    const float* conv_v_w   = (const float*)d_in[4];
    const float* conv_v_b   = (const float*)d_in[5];
    const float* row_embed  = (const float*)d_in[6];
    const float* col_embed  = (const float*)d_in[7];
    const float* lin_q_w    = (const float*)d_in[8];
    const float* lin_q_b    = (const float*)d_in[9];
    const float* lin_v_w    = (const float*)d_in[10];
    const float* lin_v_b    = (const float*)d_in[11];
    const float* msda_off_w = (const float*)d_in[12];
    const float* msda_off_b = (const float*)d_in[13];
    const float* msda_aw_w  = (const float*)d_in[14];
    const float* msda_aw_b  = (const float*)d_in[15];
    const float* msda_vp_w  = (const float*)d_in[16];
    const float* msda_vp_b  = (const float*)d_in[17];
    const float* msda_op_w  = (const float*)d_in[18];
    const float* msda_op_b  = (const float*)d_in[19];
    const float* out_w1     = (const float*)d_in[20];
    const float* out_b1     = (const float*)d_in[21];
    const float* ln1_g      = (const float*)d_in[22];
    const float* ln1_b      = (const float*)d_in[23];
    const float* out_w2     = (const float*)d_in[24];
    const float* out_b2     = (const float*)d_in[25];
    const float* ln2_g      = (const float*)d_in[26];
    const float* ln2_b      = (const float*)d_in[27];
    const float* out_w3     = (const float*)d_in[28];
    const float* out_b3     = (const float*)d_in[29];

    float* pos   = (float*)devptr(g_pos);
    float* q     = (float*)devptr(g_q);
    float* val3  = (float*)devptr(g_val3);
    float* valb  = (float*)devptr(g_val);
    float* offaw = (float*)devptr(g_offaw);
    float* h1f   = (float*)devptr(g_h1f);
    float* h2f   = (float*)devptr(g_h2f);
    float* packb = (float*)devptr(g_packb);

    __nv_bfloat16* cq_h = (__nv_bfloat16*)devptr(g_cq_h);
    __nv_bfloat16* cq_l = (__nv_bfloat16*)devptr(g_cq_l);
    __nv_bfloat16* cv_h = (__nv_bfloat16*)devptr(g_cv_h);
    __nv_bfloat16* cv_l = (__nv_bfloat16*)devptr(g_cv_l);
    __nv_bfloat16* t_h  = (__nv_bfloat16*)devptr(g_t_h);
    __nv_bfloat16* t_l  = (__nv_bfloat16*)devptr(g_t_l);
    __nv_bfloat16* vb_h = (__nv_bfloat16*)devptr(g_vb_h);
    __nv_bfloat16* vb_l = (__nv_bfloat16*)devptr(g_vb_l);
    __nv_bfloat16* qb_h = (__nv_bfloat16*)devptr(g_qb_h);
    __nv_bfloat16* qb_l = (__nv_bfloat16*)devptr(g_qb_l);
    __nv_bfloat16* qp_h = (__nv_bfloat16*)devptr(g_qp_h);
    __nv_bfloat16* qp_l = (__nv_bfloat16*)devptr(g_qp_l);
    __nv_bfloat16* sp_h = (__nv_bfloat16*)devptr(g_sp_h);
    __nv_bfloat16* sp_l = (__nv_bfloat16*)devptr(g_sp_l);
    __nv_bfloat16* h1_h = (__nv_bfloat16*)devptr(g_h1_h);
    __nv_bfloat16* h1_l = (__nv_bfloat16*)devptr(g_h1_l);
    __nv_bfloat16* h2_h = (__nv_bfloat16*)devptr(g_h2_h);
    __nv_bfloat16* h2_l = (__nv_bfloat16*)devptr(g_h2_l);
    __nv_bfloat16* w_h  = (__nv_bfloat16*)devptr(g_w_h);
    __nv_bfloat16* w_l  = (__nv_bfloat16*)devptr(g_w_l);

    const dim3 blk(256);

    cudaFuncSetAttribute(gemm_mma<64, false, true,  false, false, false>, cudaFuncAttributeMaxDynamicSharedMemorySize, SMEM64);
    cudaFuncSetAttribute(gemm_mma<64, true,  false, false, false, true >, cudaFuncAttributeMaxDynamicSharedMemorySize, SMEM64);
    cudaFuncSetAttribute(gemm_mma<64, true,  false, false, false, false>, cudaFuncAttributeMaxDynamicSharedMemorySize, SMEM64);
    cudaFuncSetAttribute(gemm_mma<32, true,  false, false, false, false>, cudaFuncAttributeMaxDynamicSharedMemorySize, SMEM32);
    cudaFuncSetAttribute(gemm_mma<64, true,  false, true,  false, true >, cudaFuncAttributeMaxDynamicSharedMemorySize, SMEM64);
    cudaFuncSetAttribute(gemm_mma<64, true,  true,  true,  false, true >, cudaFuncAttributeMaxDynamicSharedMemorySize, SMEM64);
    cudaFuncSetAttribute(gemm_mma<64, false, true,  true,  false, false>, cudaFuncAttributeMaxDynamicSharedMemorySize, SMEM64);
    cudaFuncSetAttribute(gemm_mma<64, true,  false, false, true,  false>, cudaFuncAttributeMaxDynamicSharedMemorySize, SMEM64);

    WPtrs wp;
    wp.p[0] = conv_q_w; wp.p[1] = conv_v_w; wp.p[2] = lin_q_w; wp.p[3] = lin_v_w;
    wp.p[4] = msda_vp_w; wp.p[5] = msda_off_w; wp.p[6] = msda_aw_w; wp.p[7] = msda_op_w;
    wp.p[8] = out_w1; wp.p[9] = out_w2; wp.p[10] = out_w3;
    convert_weights_kernel<<<(W_TOTAL + 255) / 256, blk>>>(wp, w_h, w_l);

    pos_kernel<<<(NQ * D + 255) / 256, blk>>>(row_embed, col_embed, pos);
    packb_kernel<<<1, 384>>>(msda_off_b, msda_aw_b, packb);

    tconvert_kernel<<<dim3(NQ / 32, CINC / 32), dim3(32, 8)>>>(query, cq_h, cq_l, NQ, CINC);
    tconvert_kernel<<<dim3(NQ / 32, CINC / 32), dim3(32, 8)>>>(value, cv_h, cv_l, NQ, CINC);

    // conv_q -> t (bf16); lin_q -> q (fp32) + qp (bf16, fused pos add)
    gemm_mma<64, false, true, false, false, false><<<dim3(4, 128), blk, SMEM64>>>(
        cq_h, cq_l, w_h + W_CONVQ, w_l + W_CONVQ, conv_q_b, nullptr,
        nullptr, t_h, t_l, nullptr, nullptr, nullptr, NQ, D, CINC);
    gemm_mma<64, true, false, false, false, true><<<dim3(4, 128), blk, SMEM64>>>(
        t_h, t_l, w_h + W_LINQ, w_l + W_LINQ, lin_q_b, nullptr,
        q, nullptr, nullptr, pos, qp_h, qp_l, NQ, D, D);
    // conv_v -> t; lin_v -> vb (bf16)
    gemm_mma<64, false, true, false, false, false><<<dim3(4, 128), blk, SMEM64>>>(
        cv_h, cv_l, w_h + W_CONVV, w_l + W_CONVV, conv_v_b, nullptr,
        nullptr, t_h, t_l, nullptr, nullptr, nullptr, NQ, D, CINC);
    gemm_mma<64, false, true, false, false, false><<<dim3(4, 128), blk, SMEM64>>>(
        t_h, t_l, w_h + W_LINV, w_l + W_LINV, lin_v_b, nullptr,
        nullptr, vb_h, vb_l, nullptr, nullptr, nullptr, NQ, D, D);

    // merged vp for cross layers 0-2: N=768 (weights + biases contiguous)
    gemm_mma<64, true, false, false, false, false><<<dim3(12, 128), blk, SMEM64>>>(
        vb_h, vb_l, w_h + W_VP, w_l + W_VP, msda_vp_b, nullptr,
        val3, nullptr, nullptr, nullptr, nullptr, nullptr, NQ, 768, D);

    // 4 MSDeformAttn layers (3 cross + 1 self)
    for (int i = 0; i < 4; i++) {
        if (i == 3) {
            // self-layer vp uses qb
            gemm_mma<64, true, false, false, false, false><<<dim3(4, 128), blk, SMEM64>>>(
                qb_h, qb_l, w_h + W_VP + 3 * 65536, w_l + W_VP + 3 * 65536,
                msda_vp_b + (size_t)3 * D, nullptr, valb,
                nullptr, nullptr, nullptr, nullptr, nullptr, NQ, D, D);
        }

        // merged off(64)+aw(32) GEMM: N=96
        gemm_mma<32, true, false, false, false, false><<<dim3(3, 128), blk, SMEM32>>>(
            qp_h, qp_l, w_h + W_OFFAW + i * 24576, w_l + W_OFFAW + i * 24576,
            packb + i * 96, nullptr, offaw,
            nullptr, nullptr, nullptr, nullptr, nullptr, NQ, 96, D);

        softmax4_kernel<<<(NQ * NHD + 255) / 256, blk>>>(offaw);

        if (i < 3)
            msda_sample_kernel<<<(NQ * NHD * 32 + 255) / 256, blk>>>(
                val3 + i * 256, 768, offaw, sp_h, sp_l);
        else
            msda_sample_kernel<<<(NQ * NHD * 32 + 255) / 256, blk>>>(
                valb, 256, offaw, sp_h, sp_l);

        // op-proj with residual; layers 0-2 fuse qp = split(q_new + pos)
        if (i < 2) {
            gemm_mma<64, true, false, true, false, true><<<dim3(4, 128), blk, SMEM64>>>(
                sp_h, sp_l, w_h + W_OP + i * 65536, w_l + W_OP + i * 65536,
                msda_op_b + (size_t)i * D, q, q, nullptr, nullptr,
                pos, qp_h, qp_l, NQ, D, D);
        } else if (i == 2) {
            gemm_mma<64, true, true, true, false, true><<<dim3(4, 128), blk, SMEM64>>>(
                sp_h, sp_l, w_h + W_OP + 2 * 65536, w_l + W_OP + 2 * 65536,
                msda_op_b + (size_t)2 * D, q, q, qb_h, qb_l,
                pos, qp_h, qp_l, NQ, D, D);
        } else {
            gemm_mma<64, false, true, true, false, false><<<dim3(4, 128), blk, SMEM64>>>(
                sp_h, sp_l, w_h + W_OP + 3 * 65536, w_l + W_OP + 3 * 65536,
                msda_op_b + (size_t)3 * D, q, nullptr, qb_h, qb_l,
                nullptr, nullptr, nullptr, NQ, D, D);
        }
    }

    // output MLP: 256 -> 128 (LN+ReLU) -> 64 (LN+ReLU) -> 384 (transposed store)
    gemm_mma<64, true, false, false, false, false><<<dim3(2, 128), blk, SMEM64>>>(
        qb_h, qb_l, w_h + W_O1, w_l + W_O1, out_b1, nullptr,
        h1f, nullptr, nullptr, nullptr, nullptr, nullptr, NQ, 128, D);
    ln_relu_kernel<128><<<(NQ * 32 + 255) / 256, blk>>>(h1f, ln1_g, ln1_b, h1_h, h1_l);
    gemm_mma<64, true, false, false, false, false><<<dim3(1, 128), blk, SMEM64>>>(
        h1_h, h1_l, w_h + W_O2, w_l + W_O2, out_b2, nullptr,
        h2f, nullptr, nullptr, nullptr, nullptr, nullptr, NQ, 64, 128);
    ln_relu_kernel<64><<<(NQ * 32 + 255) / 256, blk>>>(h2f, ln2_g, ln2_b, h2_h, h2_l);
    gemm_mma<64, true, false, false, true, false><<<dim3(6, 128), blk, SMEM64>>>(
        h2_h, h2_l, w_h + W_O3, w_l + W_O3, out_b3, nullptr,
        (float*)d_out, nullptr, nullptr, nullptr, nullptr, nullptr, NQ, CINC, 64);
}